// round 1
// baseline (speedup 1.0000x reference)
#include <cuda_runtime.h>
#include <math.h>

#define BQ    16384
#define DVIS  1024
#define DH    256
#define NE    4
#define NG    5000
#define NMAP  128
#define NSCVI 30
#define H4    1024   // 4*DH

// ---------------- scratch (device globals; no allocation allowed) ----------
__device__ float g_z [(size_t)BQ * DH];   // encoder output z
__device__ float g_zf[(size_t)BQ * DH];   // z_final = z + gated expert out
__device__ float g_h [(size_t)BQ * H4];   // expert hidden
__device__ float g_t [(size_t)BQ * DH];   // gene-decoder hidden (pre/post LN)
__device__ float g_gate[BQ];
__device__ int   g_list[NE * BQ];
__device__ int   g_cnt[NE];

// ---------------- math helpers --------------------------------------------
__device__ __forceinline__ float gelu_f(float x) {
    return 0.5f * x * (1.0f + erff(x * 0.70710678118654752440f));
}
__device__ __forceinline__ float softplus_f(float x) {
    return (x > 20.0f) ? x : log1pf(expf(x));
}

// ---------------- positional Fourier encoder -------------------------------
// g_z[r, :] = gelu( [sin,cos](2pi * pos @ fB) @ pos_W + pos_b )
__global__ __launch_bounds__(256)
void posenc_k(const float* __restrict__ pos, const float* __restrict__ fB,
              const float* __restrict__ pW, const float* __restrict__ pb)
{
    __shared__ float four_s[32][256];
    __shared__ float pos_s[32][3];
    int tid = threadIdx.x;
    int r0  = blockIdx.x * 32;
    if (tid < 96) pos_s[tid / 3][tid % 3] = pos[(size_t)r0 * 3 + tid];
    __syncthreads();
    #pragma unroll
    for (int i = 0; i < 32; i++) {
        int c = tid;
        int m = c & 127;
        float xp = 6.283185307179586f *
                   (pos_s[i][0] * fB[m] + pos_s[i][1] * fB[128 + m] + pos_s[i][2] * fB[256 + m]);
        four_s[i][c] = (c < 128) ? sinf(xp) : cosf(xp);
    }
    __syncthreads();
    float acc[32];
    float bb = pb[tid];
    #pragma unroll
    for (int rr = 0; rr < 32; rr++) acc[rr] = bb;
    for (int k = 0; k < 256; k++) {
        float w = pW[k * 256 + tid];
        #pragma unroll
        for (int rr = 0; rr < 32; rr++) acc[rr] += four_s[rr][k] * w;
    }
    #pragma unroll
    for (int rr = 0; rr < 32; rr++)
        g_z[(size_t)(r0 + rr) * DH + tid] = gelu_f(acc[rr]);
}

// ---------------- generic 128x64 fp32 tiled GEMM ---------------------------
// C = A[M,K] @ W[K,N]  (+ epilogue per MODE)
// MODE 0: C[r,c] = acc + bias[c] + extra[r,c]         (vis encoder, in-place add into g_z)
// MODE 1: C[r,c] = acc + bias[c]                      (gd1 pre-LN)
// MODE 2: gene decoder head: pair columns -> mu/theta with softplus, extra = library_size
template<int MODE>
__global__ __launch_bounds__(256)
void gemm_k(const float* __restrict__ A, const float* __restrict__ W,
            const float* __restrict__ bias, const float* __restrict__ extra,
            float* __restrict__ C, int M, int N, int K)
{
    const int BM = 128, BN = 64, BK = 16;
    __shared__ float As[BK][BM];
    __shared__ float Bs[BK][BN];
    int tid  = threadIdx.x;
    int row0 = blockIdx.x * BM;
    int col0 = blockIdx.y * BN;
    int ty = tid >> 4, tx = tid & 15;
    float acc[8][4];
    #pragma unroll
    for (int i = 0; i < 8; i++)
        #pragma unroll
        for (int j = 0; j < 4; j++) acc[i][j] = 0.0f;

    for (int kt = 0; kt < K; kt += BK) {
        #pragma unroll
        for (int i = 0; i < 2; i++) {
            int f4 = tid * 2 + i;
            int ar = f4 >> 2;
            int ak = (f4 & 3) << 2;
            float4 v = *reinterpret_cast<const float4*>(A + (size_t)(row0 + ar) * K + kt + ak);
            As[ak + 0][ar] = v.x; As[ak + 1][ar] = v.y;
            As[ak + 2][ar] = v.z; As[ak + 3][ar] = v.w;
        }
        {
            int kk = tid >> 4;
            int c4 = (tid & 15) << 2;
            int gc = col0 + c4;
            const float* wp = W + (size_t)(kt + kk) * N + gc;
            float4 v;
            if (gc + 3 < N) v = *reinterpret_cast<const float4*>(wp);
            else {
                v.x = (gc     < N) ? wp[0] : 0.0f;
                v.y = (gc + 1 < N) ? wp[1] : 0.0f;
                v.z = (gc + 2 < N) ? wp[2] : 0.0f;
                v.w = (gc + 3 < N) ? wp[3] : 0.0f;
            }
            *reinterpret_cast<float4*>(&Bs[kk][c4]) = v;
        }
        __syncthreads();
        #pragma unroll
        for (int k = 0; k < BK; k++) {
            float4 a0 = *reinterpret_cast<const float4*>(&As[k][ty * 8]);
            float4 a1 = *reinterpret_cast<const float4*>(&As[k][ty * 8 + 4]);
            float4 b0 = *reinterpret_cast<const float4*>(&Bs[k][tx * 4]);
            float av[8] = {a0.x, a0.y, a0.z, a0.w, a1.x, a1.y, a1.z, a1.w};
            float bv[4] = {b0.x, b0.y, b0.z, b0.w};
            #pragma unroll
            for (int i = 0; i < 8; i++)
                #pragma unroll
                for (int j = 0; j < 4; j++)
                    acc[i][j] += av[i] * bv[j];
        }
        __syncthreads();
    }
    #pragma unroll
    for (int i = 0; i < 8; i++) {
        int r = row0 + ty * 8 + i;
        #pragma unroll
        for (int j = 0; j < 4; j++) {
            int c = col0 + tx * 4 + j;
            if (c >= N) continue;
            float v = acc[i][j] + bias[c];
            if (MODE == 0) {
                C[(size_t)r * N + c] = v + extra[(size_t)r * N + c];
            } else if (MODE == 1) {
                C[(size_t)r * N + c] = v;
            } else {
                float sp = softplus_f(v);
                int gidx = c >> 1;
                if ((c & 1) == 0)
                    C[(size_t)r * NG + gidx] = sp * extra[r] + 1e-6f;   // mu
                else
                    C[(size_t)BQ * NG + (size_t)r * NG + gidx] = sp + 1e-6f; // theta
            }
        }
    }
}

// ---------------- router: logits=[z,grad]@rout_W+b, top-1 gate + compaction -
__global__ __launch_bounds__(256)
void router_k(const float* __restrict__ grad,
              const float* __restrict__ rW, const float* __restrict__ rb)
{
    int warp = threadIdx.x >> 5, lane = threadIdx.x & 31;
    int r = blockIdx.x * 8 + warp;
    const float* zr = g_z + (size_t)r * DH;
    float s0 = 0.f, s1 = 0.f, s2 = 0.f, s3 = 0.f;
    for (int k = lane; k < DH; k += 32) {
        float zv = zr[k];
        const float* w = rW + k * 4;
        s0 += zv * w[0]; s1 += zv * w[1]; s2 += zv * w[2]; s3 += zv * w[3];
    }
    if (lane == 0) {
        float gv = grad[r];
        const float* w = rW + 256 * 4;
        s0 += gv * w[0]; s1 += gv * w[1]; s2 += gv * w[2]; s3 += gv * w[3];
    }
    for (int o = 16; o > 0; o >>= 1) {
        s0 += __shfl_down_sync(0xffffffffu, s0, o);
        s1 += __shfl_down_sync(0xffffffffu, s1, o);
        s2 += __shfl_down_sync(0xffffffffu, s2, o);
        s3 += __shfl_down_sync(0xffffffffu, s3, o);
    }
    if (lane == 0) {
        float l[4] = {s0 + rb[0], s1 + rb[1], s2 + rb[2], s3 + rb[3]};
        int best = 0; float m = l[0];
        #pragma unroll
        for (int e = 1; e < 4; e++) if (l[e] > m) { m = l[e]; best = e; }
        float sum = 0.f;
        #pragma unroll
        for (int e = 0; e < 4; e++) sum += expf(l[e] - m);
        g_gate[r] = 1.0f / sum;            // = softmax max prob
        int pos = atomicAdd(&g_cnt[best], 1);
        g_list[best * BQ + pos] = r;
    }
}

__global__ void zero_cnt_k() { if (threadIdx.x < NE) g_cnt[threadIdx.x] = 0; }

// ---------------- MoE grouped GEMM (gathered rows, selected expert only) ----
// MODE 0: g_h[gr,:]  = gelu( g_z[gr,:] @ e_W1[e] + e_b1[e] )      K=256, N=1024
// MODE 1: g_zf[gr,:] = g_z[gr,:] + gate[gr]*( g_h[gr,:] @ e_W2[e] + e_b2[e] )  K=1024, N=256
template<int MODE>
__global__ __launch_bounds__(256)
void moe_gemm_k(const float* __restrict__ W_all, const float* __restrict__ bias_all)
{
    constexpr int K = (MODE == 0) ? DH : H4;
    constexpr int N = (MODE == 0) ? H4 : DH;
    const int BM = 128, BN = 64, BK = 16;
    int e  = blockIdx.z;
    int Me = g_cnt[e];
    int row0 = blockIdx.x * BM;
    if (row0 >= Me) return;
    const float* A    = (MODE == 0) ? g_z : g_h;
    const float* W    = W_all   + (size_t)e * K * N;
    const float* bias = bias_all + (size_t)e * N;

    __shared__ float As[BK][BM];
    __shared__ float Bs[BK][BN];
    __shared__ int   ridx[BM];
    int tid = threadIdx.x;
    if (tid < BM) {
        int rr = row0 + tid;
        if (rr > Me - 1) rr = Me - 1;
        ridx[tid] = g_list[e * BQ + rr];
    }
    __syncthreads();

    int col0 = blockIdx.y * BN;
    int ty = tid >> 4, tx = tid & 15;
    float acc[8][4];
    #pragma unroll
    for (int i = 0; i < 8; i++)
        #pragma unroll
        for (int j = 0; j < 4; j++) acc[i][j] = 0.0f;

    for (int kt = 0; kt < K; kt += BK) {
        #pragma unroll
        for (int i = 0; i < 2; i++) {
            int f4 = tid * 2 + i;
            int ar = f4 >> 2;
            int ak = (f4 & 3) << 2;
            float4 v = *reinterpret_cast<const float4*>(A + (size_t)ridx[ar] * K + kt + ak);
            As[ak + 0][ar] = v.x; As[ak + 1][ar] = v.y;
            As[ak + 2][ar] = v.z; As[ak + 3][ar] = v.w;
        }
        {
            int kk = tid >> 4;
            int c4 = (tid & 15) << 2;
            float4 v = *reinterpret_cast<const float4*>(W + (size_t)(kt + kk) * N + col0 + c4);
            *reinterpret_cast<float4*>(&Bs[kk][c4]) = v;
        }
        __syncthreads();
        #pragma unroll
        for (int k = 0; k < BK; k++) {
            float4 a0 = *reinterpret_cast<const float4*>(&As[k][ty * 8]);
            float4 a1 = *reinterpret_cast<const float4*>(&As[k][ty * 8 + 4]);
            float4 b0 = *reinterpret_cast<const float4*>(&Bs[k][tx * 4]);
            float av[8] = {a0.x, a0.y, a0.z, a0.w, a1.x, a1.y, a1.z, a1.w};
            float bv[4] = {b0.x, b0.y, b0.z, b0.w};
            #pragma unroll
            for (int i = 0; i < 8; i++)
                #pragma unroll
                for (int j = 0; j < 4; j++)
                    acc[i][j] += av[i] * bv[j];
        }
        __syncthreads();
    }
    #pragma unroll
    for (int i = 0; i < 8; i++) {
        int lr = ty * 8 + i;
        if (row0 + lr >= Me) continue;
        int gr = ridx[lr];
        #pragma unroll
        for (int j = 0; j < 4; j++) {
            int c = col0 + tx * 4 + j;
            float v = acc[i][j] + bias[c];
            if (MODE == 0) {
                g_h[(size_t)gr * H4 + c] = gelu_f(v);
            } else {
                g_zf[(size_t)gr * DH + c] = g_z[(size_t)gr * DH + c] + g_gate[gr] * v;
            }
        }
    }
}

// ---------------- LayerNorm + GELU over g_t rows ----------------------------
__global__ __launch_bounds__(256)
void ln_gelu_k(const float* __restrict__ g, const float* __restrict__ beta)
{
    int r = blockIdx.x, tid = threadIdx.x;
    float x = g_t[(size_t)r * DH + tid];
    __shared__ float red[8];
    __shared__ float stat[2];
    float s = x;
    for (int o = 16; o > 0; o >>= 1) s += __shfl_down_sync(0xffffffffu, s, o);
    if ((tid & 31) == 0) red[tid >> 5] = s;
    __syncthreads();
    if (tid == 0) {
        float t = 0.f;
        for (int i = 0; i < 8; i++) t += red[i];
        stat[0] = t * (1.0f / 256.0f);
    }
    __syncthreads();
    float mu = stat[0];
    float d  = x - mu;
    s = d * d;
    for (int o = 16; o > 0; o >>= 1) s += __shfl_down_sync(0xffffffffu, s, o);
    if ((tid & 31) == 0) red[tid >> 5] = s;
    __syncthreads();
    if (tid == 0) {
        float t = 0.f;
        for (int i = 0; i < 8; i++) t += red[i];
        stat[1] = t * (1.0f / 256.0f);
    }
    __syncthreads();
    float y = g[tid] * d * rsqrtf(stat[1] + 1e-5f) + beta[tid];
    g_t[(size_t)r * DH + tid] = gelu_f(y);
}

// ---------------- func head: sigmoid(gelu(zf@W1+b1)@W2+b2) ------------------
__global__ __launch_bounds__(64)
void func_k(const float* __restrict__ W1, const float* __restrict__ b1,
            const float* __restrict__ W2, const float* __restrict__ b2,
            float* __restrict__ outp)
{
    __shared__ float zf_s[8][256];
    __shared__ float fw[8][64];
    int tid = threadIdx.x;
    int r0  = blockIdx.x * 8;
    for (int i = tid; i < 8 * 256; i += 64)
        zf_s[i >> 8][i & 255] = g_zf[(size_t)r0 * DH + i];
    __syncthreads();
    float acc[8];
    float bb = b1[tid];
    #pragma unroll
    for (int rr = 0; rr < 8; rr++) acc[rr] = bb;
    for (int k = 0; k < 256; k++) {
        float w = W1[k * 64 + tid];
        #pragma unroll
        for (int rr = 0; rr < 8; rr++) acc[rr] += zf_s[rr][k] * w;
    }
    float w2 = W2[tid];
    #pragma unroll
    for (int rr = 0; rr < 8; rr++) fw[rr][tid] = gelu_f(acc[rr]) * w2;
    __syncthreads();
    if (tid < 8) {
        float s = b2[0];
        for (int j = 0; j < 64; j++) s += fw[tid][j];
        outp[r0 + tid] = 1.0f / (1.0f + expf(-s));
    }
}

// ---------------- align head: gelu(zf@W1+b1)@W2+b2 --------------------------
__global__ __launch_bounds__(128)
void align_k(const float* __restrict__ W1, const float* __restrict__ b1,
             const float* __restrict__ W2, const float* __restrict__ b2,
             float* __restrict__ outp)
{
    __shared__ float zf_s[8][256];
    __shared__ float a1_s[8][128];
    int tid = threadIdx.x;
    int r0  = blockIdx.x * 8;
    for (int i = tid; i < 8 * 256; i += 128)
        zf_s[i >> 8][i & 255] = g_zf[(size_t)r0 * DH + i];
    __syncthreads();
    float acc[8];
    float bb = b1[tid];
    #pragma unroll
    for (int rr = 0; rr < 8; rr++) acc[rr] = bb;
    for (int k = 0; k < 256; k++) {
        float w = W1[k * 128 + tid];
        #pragma unroll
        for (int rr = 0; rr < 8; rr++) acc[rr] += zf_s[rr][k] * w;
    }
    #pragma unroll
    for (int rr = 0; rr < 8; rr++) a1_s[rr][tid] = gelu_f(acc[rr]);
    __syncthreads();
    for (int idx = tid; idx < 8 * NSCVI; idx += 128) {
        int rr = idx / NSCVI, o = idx % NSCVI;
        float s = b2[o];
        for (int k = 0; k < 128; k++) s += a1_s[rr][k] * W2[k * NSCVI + o];
        outp[(size_t)(r0 + rr) * NSCVI + o] = s;
    }
}

// ---------------- launch ----------------------------------------------------
extern "C" void kernel_launch(void* const* d_in, const int* in_sizes, int n_in,
                              void* d_out, int out_size)
{
    const float* vis   = (const float*)d_in[0];
    const float* pos   = (const float*)d_in[1];
    const float* grad  = (const float*)d_in[2];
    const float* lib   = (const float*)d_in[3];
    const float* fB    = (const float*)d_in[4];
    const float* imgW  = (const float*)d_in[5];
    const float* imgb  = (const float*)d_in[6];
    const float* posW  = (const float*)d_in[7];
    const float* posb  = (const float*)d_in[8];
    const float* routW = (const float*)d_in[9];
    const float* routb = (const float*)d_in[10];
    const float* eW1   = (const float*)d_in[11];
    const float* eb1   = (const float*)d_in[12];
    const float* eW2   = (const float*)d_in[13];
    const float* eb2   = (const float*)d_in[14];
    const float* gdW1  = (const float*)d_in[15];
    const float* gdb1  = (const float*)d_in[16];
    const float* gdg   = (const float*)d_in[17];
    const float* gdbe  = (const float*)d_in[18];
    const float* gdW2  = (const float*)d_in[19];
    const float* gdb2  = (const float*)d_in[20];
    const float* apW1  = (const float*)d_in[21];
    const float* apb1  = (const float*)d_in[22];
    const float* apW2  = (const float*)d_in[23];
    const float* apb2  = (const float*)d_in[24];
    const float* fhW1  = (const float*)d_in[25];
    const float* fhb1  = (const float*)d_in[26];
    const float* fhW2  = (const float*)d_in[27];
    const float* fhb2  = (const float*)d_in[28];
    float* out = (float*)d_out;

    float *zp, *zfp, *tp;
    cudaGetSymbolAddress((void**)&zp,  g_z);
    cudaGetSymbolAddress((void**)&zfp, g_zf);
    cudaGetSymbolAddress((void**)&tp,  g_t);

    // 1. positional encoder -> g_z
    posenc_k<<<BQ / 32, 256>>>(pos, fB, posW, posb);
    // 2. z += vis @ img_W + img_b
    gemm_k<0><<<dim3(BQ / 128, DH / 64), 256>>>(vis, imgW, imgb, zp, zp, BQ, DH, DVIS);
    // 3. router: top-1 expert, gate, per-expert row lists
    zero_cnt_k<<<1, 32>>>();
    router_k<<<BQ / 8, 256>>>(grad, routW, routb);
    // 4. MoE (selected expert only), grouped GEMMs over gathered rows
    moe_gemm_k<0><<<dim3(BQ / 128, H4 / 64, NE), 256>>>(eW1, eb1);
    moe_gemm_k<1><<<dim3(BQ / 128, DH / 64, NE), 256>>>(eW2, eb2);
    // 5. gene decoder: t = zf @ gd_W1 + b1 ; LN ; gelu
    gemm_k<1><<<dim3(BQ / 128, DH / 64), 256>>>(zfp, gdW1, gdb1, nullptr, tp, BQ, DH, DH);
    ln_gelu_k<<<BQ, 256>>>(gdg, gdbe);
    // 6. gd2: preds -> mu/theta (dominant GEMM, N=10000)
    gemm_k<2><<<dim3(BQ / 128, (2 * NG + 63) / 64), 256>>>(tp, gdW2, gdb2, lib, out, BQ, 2 * NG, DH);
    // 7. heads
    func_k<<<BQ / 8, 64>>>(fhW1, fhb1, fhW2, fhb2, out + (size_t)2 * BQ * NG);
    align_k<<<BQ / 8, 128>>>(apW1, apb1, apW2, apb2, out + (size_t)2 * BQ * NG + BQ);
}